// round 1
// baseline (speedup 1.0000x reference)
#include <cuda_runtime.h>
#include <math.h>

// Problem constants
#define TT   2048          // sequence length
#define CC   4096          // model dim
#define NH   32            // heads
#define HS   128           // head size
#define NEr  32            // rope dims
#define QKVN 12288         // 3*C

// Scratch (no cudaMalloc allowed)
__device__ float g_qkv[(size_t)TT * QKVN];   // [T, 3C]  (h*384 + m*128 + d)
__device__ float g_y  [(size_t)TT * CC];     // [T, C]   attention output

// ---------------------------------------------------------------------------
// GEMM: C[M,N] = A[M,K] @ B[N,K]^T + bias[N]
// A row-major [M,K], B row-major [N,K]. M,N multiples of 128, K multiple of 8.
// 128x128x8 tile, 8x8 microtile, 256 threads, global prefetch.
// ---------------------------------------------------------------------------
__global__ __launch_bounds__(256, 2)
void gemm_nt(const float* __restrict__ A, const float* __restrict__ B,
             const float* __restrict__ bias, float* __restrict__ Cm,
             int M, int N, int K) {
    __shared__ float As[8][128];
    __shared__ float Bs[8][128];

    const int tid = threadIdx.x;
    const int tx  = tid & 15;          // 0..15 -> N microtile
    const int ty  = tid >> 4;          // 0..15 -> M microtile
    const int bx  = blockIdx.x;        // N tile
    const int by  = blockIdx.y;        // M tile

    const int lrow = tid >> 1;         // 0..127
    const int lseg = (tid & 1) << 2;   // 0 or 4

    const float* Ag = A + (size_t)(by * 128 + lrow) * K + lseg;
    const float* Bg = B + (size_t)(bx * 128 + lrow) * K + lseg;

    float4 av = *(const float4*)Ag;
    float4 bv = *(const float4*)Bg;

    float acc[8][8];
    #pragma unroll
    for (int i = 0; i < 8; i++)
        #pragma unroll
        for (int j = 0; j < 8; j++) acc[i][j] = 0.0f;

    for (int k0 = 0; k0 < K; k0 += 8) {
        As[lseg + 0][lrow] = av.x;
        As[lseg + 1][lrow] = av.y;
        As[lseg + 2][lrow] = av.z;
        As[lseg + 3][lrow] = av.w;
        Bs[lseg + 0][lrow] = bv.x;
        Bs[lseg + 1][lrow] = bv.y;
        Bs[lseg + 2][lrow] = bv.z;
        Bs[lseg + 3][lrow] = bv.w;
        __syncthreads();

        if (k0 + 8 < K) {
            av = *(const float4*)(Ag + k0 + 8);
            bv = *(const float4*)(Bg + k0 + 8);
        }

        #pragma unroll
        for (int kk = 0; kk < 8; kk++) {
            float a[8], b[8];
            *(float4*)&a[0] = *(const float4*)&As[kk][ty << 3];
            *(float4*)&a[4] = *(const float4*)&As[kk][(ty << 3) + 4];
            *(float4*)&b[0] = *(const float4*)&Bs[kk][tx << 3];
            *(float4*)&b[4] = *(const float4*)&Bs[kk][(tx << 3) + 4];
            #pragma unroll
            for (int i = 0; i < 8; i++)
                #pragma unroll
                for (int j = 0; j < 8; j++)
                    acc[i][j] += a[i] * b[j];
        }
        __syncthreads();
    }

    const int row0 = by * 128 + (ty << 3);
    const int col0 = bx * 128 + (tx << 3);
    float bc[8];
    #pragma unroll
    for (int j = 0; j < 8; j++) bc[j] = bias[col0 + j];

    #pragma unroll
    for (int i = 0; i < 8; i++) {
        float4 r0, r1;
        r0.x = acc[i][0] + bc[0];  r0.y = acc[i][1] + bc[1];
        r0.z = acc[i][2] + bc[2];  r0.w = acc[i][3] + bc[3];
        r1.x = acc[i][4] + bc[4];  r1.y = acc[i][5] + bc[5];
        r1.z = acc[i][6] + bc[6];  r1.w = acc[i][7] + bc[7];
        *(float4*)(Cm + (size_t)(row0 + i) * N + col0)     = r0;
        *(float4*)(Cm + (size_t)(row0 + i) * N + col0 + 4) = r1;
    }
}

// ---------------------------------------------------------------------------
// RoPE, in-place on q and k slices of g_qkv.
// For each (t, h, m in {q,k}, d in [0,16)):
//   x1 = p[d], x2 = p[d+16]
//   p[d]    = x1*cos[t,d]    - x2*sin[t,d]
//   p[d+16] = x2*cos[t,d+16] + x1*sin[t,d+16]
// ---------------------------------------------------------------------------
__global__ void rope_kernel(float* __restrict__ qkv,
                            const float* __restrict__ cosp,
                            const float* __restrict__ sinp) {
    int idx = blockIdx.x * blockDim.x + threadIdx.x;
    const int total = TT * NH * 2 * 16;
    if (idx >= total) return;
    int d = idx & 15;
    int m = (idx >> 4) & 1;
    int h = (idx >> 5) & 31;
    int t = idx >> 10;
    float* p = qkv + (size_t)t * QKVN + h * 384 + m * 128;
    float x1 = p[d];
    float x2 = p[d + 16];
    float c1 = cosp[t * NEr + d];
    float s1 = sinp[t * NEr + d];
    float c2 = cosp[t * NEr + d + 16];
    float s2 = sinp[t * NEr + d + 16];
    p[d]      = x1 * c1 - x2 * s1;
    p[d + 16] = x2 * c2 + x1 * s2;
}

// ---------------------------------------------------------------------------
// Causal flash attention, fp32.
// Block = (q-tile of 64, head). 256 threads: tx = tid&15 (cols), ty = tid>>4.
// Q, K staged transposed [d][row] (stride 68) for conflict-free float4 LDS.
// V reuses K's buffer, layout [row][d] stride 132.
// Per-thread: S microtile 4x4 (rows ty*4.., cols tx*4..),
//             O microtile 4x8 (rows ty*4.., cols tx*8..).
// ---------------------------------------------------------------------------
#define QT_STRIDE 68
#define VS_STRIDE 132
#define ATTN_SMEM_FLOATS (2 * 128 * QT_STRIDE + 64 * QT_STRIDE)
#define ATTN_SMEM_BYTES  (ATTN_SMEM_FLOATS * 4)

__global__ __launch_bounds__(256)
void attn_kernel(const float* __restrict__ qkv, float* __restrict__ y) {
    const int q0 = blockIdx.x * 64;
    const int h  = blockIdx.y;

    extern __shared__ float sm[];
    float* Qt = sm;                          // [128][68]  Qt[d*68 + r]
    float* Kt = sm + 128 * QT_STRIDE;        // [128][68]  / reused as Vs[64][132]
    float* Ss = sm + 2 * 128 * QT_STRIDE;    // [64][68]

    const int tid = threadIdx.x;
    const int tx  = tid & 15;
    const int ty  = tid >> 4;
    const float scale = 0.08838834764831845f;   // 1/sqrt(128)

    // Load Q tile transposed, pre-scaled
    for (int i = tid; i < 64 * 32; i += 256) {
        int r  = i >> 5;
        int d4 = (i & 31) << 2;
        float4 v = *(const float4*)(qkv + (size_t)(q0 + r) * QKVN + h * 384 + d4);
        Qt[(d4 + 0) * QT_STRIDE + r] = v.x * scale;
        Qt[(d4 + 1) * QT_STRIDE + r] = v.y * scale;
        Qt[(d4 + 2) * QT_STRIDE + r] = v.z * scale;
        Qt[(d4 + 3) * QT_STRIDE + r] = v.w * scale;
    }

    float m_[4], l_[4], o_[4][8];
    #pragma unroll
    for (int i = 0; i < 4; i++) {
        m_[i] = -1e30f;
        l_[i] = 0.0f;
        #pragma unroll
        for (int j = 0; j < 8; j++) o_[i][j] = 0.0f;
    }

    for (int k0 = 0; k0 <= q0; k0 += 64) {
        __syncthreads();   // prior V reads done (and Q visible on first iter)

        // Load K tile transposed
        for (int i = tid; i < 64 * 32; i += 256) {
            int r  = i >> 5;
            int d4 = (i & 31) << 2;
            float4 v = *(const float4*)(qkv + (size_t)(k0 + r) * QKVN + h * 384 + 128 + d4);
            Kt[(d4 + 0) * QT_STRIDE + r] = v.x;
            Kt[(d4 + 1) * QT_STRIDE + r] = v.y;
            Kt[(d4 + 2) * QT_STRIDE + r] = v.z;
            Kt[(d4 + 3) * QT_STRIDE + r] = v.w;
        }
        __syncthreads();

        // S = Q K^T  (4x4 per thread)
        float acc[4][4];
        #pragma unroll
        for (int i = 0; i < 4; i++)
            #pragma unroll
            for (int j = 0; j < 4; j++) acc[i][j] = 0.0f;

        #pragma unroll 4
        for (int d = 0; d < 128; d++) {
            float4 a4 = *(const float4*)(Qt + d * QT_STRIDE + (ty << 2));
            float4 b4 = *(const float4*)(Kt + d * QT_STRIDE + (tx << 2));
            float a[4] = {a4.x, a4.y, a4.z, a4.w};
            float b[4] = {b4.x, b4.y, b4.z, b4.w};
            #pragma unroll
            for (int i = 0; i < 4; i++)
                #pragma unroll
                for (int j = 0; j < 4; j++)
                    acc[i][j] += a[i] * b[j];
        }

        // Causal mask (diagonal tile only)
        if (k0 == q0) {
            #pragma unroll
            for (int i = 0; i < 4; i++)
                #pragma unroll
                for (int j = 0; j < 4; j++)
                    if ((tx << 2) + j > (ty << 2) + i) acc[i][j] = -1e30f;
        }

        // Online softmax (rows owned by ty group; reduce over 16 tx lanes)
        #pragma unroll
        for (int i = 0; i < 4; i++) {
            float mx = fmaxf(fmaxf(acc[i][0], acc[i][1]), fmaxf(acc[i][2], acc[i][3]));
            #pragma unroll
            for (int ofs = 8; ofs >= 1; ofs >>= 1)
                mx = fmaxf(mx, __shfl_xor_sync(0xffffffffu, mx, ofs));
            float mn = fmaxf(m_[i], mx);
            float al = __expf(m_[i] - mn);
            float sum = 0.0f;
            #pragma unroll
            for (int j = 0; j < 4; j++) {
                float p = __expf(acc[i][j] - mn);
                acc[i][j] = p;
                sum += p;
            }
            #pragma unroll
            for (int ofs = 8; ofs >= 1; ofs >>= 1)
                sum += __shfl_xor_sync(0xffffffffu, sum, ofs);
            l_[i] = l_[i] * al + sum;
            m_[i] = mn;
            #pragma unroll
            for (int j = 0; j < 8; j++) o_[i][j] *= al;
            #pragma unroll
            for (int j = 0; j < 4; j++)
                Ss[((ty << 2) + i) * QT_STRIDE + (tx << 2) + j] = acc[i][j];
        }
        __syncthreads();   // Ss written; Kt reads complete

        // Load V tile into Kt buffer, layout [row][d] stride 132
        float* Vs = Kt;
        for (int i = tid; i < 64 * 32; i += 256) {
            int r  = i >> 5;
            int d4 = (i & 31) << 2;
            *(float4*)(Vs + r * VS_STRIDE + d4) =
                *(const float4*)(qkv + (size_t)(k0 + r) * QKVN + h * 384 + 256 + d4);
        }
        __syncthreads();

        // O += P @ V   (4 rows x 8 cols per thread)
        for (int kk = 0; kk < 64; kk += 4) {
            float pr[4][4];
            #pragma unroll
            for (int i = 0; i < 4; i++)
                *(float4*)&pr[i][0] =
                    *(const float4*)&Ss[((ty << 2) + i) * QT_STRIDE + kk];
            #pragma unroll
            for (int c = 0; c < 4; c++) {
                float4 v0 = *(const float4*)(Vs + (kk + c) * VS_STRIDE + (tx << 3));
                float4 v1 = *(const float4*)(Vs + (kk + c) * VS_STRIDE + (tx << 3) + 4);
                #pragma unroll
                for (int i = 0; i < 4; i++) {
                    float p = pr[i][c];
                    o_[i][0] += p * v0.x;  o_[i][1] += p * v0.y;
                    o_[i][2] += p * v0.z;  o_[i][3] += p * v0.w;
                    o_[i][4] += p * v1.x;  o_[i][5] += p * v1.y;
                    o_[i][6] += p * v1.z;  o_[i][7] += p * v1.w;
                }
            }
        }
    }

    // Epilogue: normalize and write y[t, h*128 + col]
    #pragma unroll
    for (int i = 0; i < 4; i++) {
        float inv = 1.0f / l_[i];
        int r = q0 + (ty << 2) + i;
        float4 w0, w1;
        w0.x = o_[i][0] * inv;  w0.y = o_[i][1] * inv;
        w0.z = o_[i][2] * inv;  w0.w = o_[i][3] * inv;
        w1.x = o_[i][4] * inv;  w1.y = o_[i][5] * inv;
        w1.z = o_[i][6] * inv;  w1.w = o_[i][7] * inv;
        *(float4*)(y + (size_t)r * CC + h * HS + (tx << 3))     = w0;
        *(float4*)(y + (size_t)r * CC + h * HS + (tx << 3) + 4) = w1;
    }
}

// ---------------------------------------------------------------------------
// Launch
// ---------------------------------------------------------------------------
extern "C" void kernel_launch(void* const* d_in, const int* in_sizes, int n_in,
                              void* d_out, int out_size) {
    const float* x      = (const float*)d_in[0];
    const float* cosp   = (const float*)d_in[1];
    const float* sinp   = (const float*)d_in[2];
    const float* W_attn = (const float*)d_in[3];
    const float* b_attn = (const float*)d_in[4];
    const float* W_proj = (const float*)d_in[5];
    const float* b_proj = (const float*)d_in[6];
    float* out = (float*)d_out;

    float *qkv_p, *y_p;
    cudaGetSymbolAddress((void**)&qkv_p, g_qkv);
    cudaGetSymbolAddress((void**)&y_p, g_y);

    cudaFuncSetAttribute(attn_kernel,
                         cudaFuncAttributeMaxDynamicSharedMemorySize,
                         ATTN_SMEM_BYTES);

    // 1) QKV = x @ W_attn^T + b_attn        [2048, 12288]
    gemm_nt<<<dim3(QKVN / 128, TT / 128), 256>>>(x, W_attn, b_attn, qkv_p,
                                                 TT, QKVN, CC);

    // 2) RoPE in-place on q, k
    rope_kernel<<<(TT * NH * 2 * 16) / 256, 256>>>(qkv_p, cosp, sinp);

    // 3) Causal attention -> y              [2048, 4096]
    attn_kernel<<<dim3(TT / 64, NH), 256, ATTN_SMEM_BYTES>>>(qkv_p, y_p);

    // 4) out = y @ W_proj^T + b_proj        [2048, 4096]
    gemm_nt<<<dim3(CC / 128, TT / 128), 256>>>(y_p, W_proj, b_proj, out,
                                               TT, CC, CC);
}

// round 2
// speedup vs baseline: 1.5094x; 1.5094x over previous
#include <cuda_runtime.h>
#include <cuda_bf16.h>
#include <math.h>
#include <stdint.h>

// Problem constants
#define TT   2048          // sequence length
#define CC   4096          // model dim
#define NH   32            // heads
#define HS   128           // head size
#define NEr  32            // rope dims
#define QKVN 12288         // 3*C

// Scratch (no cudaMalloc allowed)
__device__ float g_qkv[(size_t)TT * QKVN];   // [T, 3C]  (h*384 + m*128 + d)
__device__ float g_y  [(size_t)TT * CC];     // [T, C]   attention output

// ===========================================================================
// Tensor-core GEMM: C[M,N] = A[M,K] @ B[N,K]^T + bias[N]
// fp32 in/out, internally split into bf16 hi+lo; 3-product compensation:
//   A*B ~= Ahi*Bhi + Ahi*Blo + Alo*Bhi   (error ~2^-18 relative)
// Block tile 128x128, 8 warps (warp tile 64m x 32n), k-stage 32 (two k16
// sub-tiles, row stride 24 bf16 = 48B: 16B-aligned, bank-conflict-free).
// Double-buffered dynamic smem (96KB), register prefetch of global loads.
// ===========================================================================

#define GSTRIDE 24                  // bf16 elems per smem row (48B)
#define SUBSZ   (128 * GSTRIDE)     // one 128x16 sub-tile = 3072 elems
#define ARRSZ   (2 * SUBSZ)         // per array per stage (k32)   = 6144
#define STAGESZ (4 * ARRSZ)         // AH, AL, BH, BL              = 24576
#define GEMM_SMEM_BYTES (2 * STAGESZ * 2)   // 2 stages * bf16     = 98304

__device__ __forceinline__ void ldsm4(uint32_t* r, const __nv_bfloat16* p) {
    uint32_t addr = (uint32_t)__cvta_generic_to_shared(p);
    asm volatile("ldmatrix.sync.aligned.m8n8.x4.shared.b16 {%0,%1,%2,%3}, [%4];"
                 : "=r"(r[0]), "=r"(r[1]), "=r"(r[2]), "=r"(r[3]) : "r"(addr));
}

__device__ __forceinline__ void mma_bf16(float* c, const uint32_t* a,
                                         uint32_t b0, uint32_t b1) {
    asm volatile(
        "mma.sync.aligned.m16n8k16.row.col.f32.bf16.bf16.f32 "
        "{%0,%1,%2,%3}, {%4,%5,%6,%7}, {%8,%9}, {%0,%1,%2,%3};\n"
        : "+f"(c[0]), "+f"(c[1]), "+f"(c[2]), "+f"(c[3])
        : "r"(a[0]), "r"(a[1]), "r"(a[2]), "r"(a[3]), "r"(b0), "r"(b1));
}

__global__ __launch_bounds__(256, 1)
void gemm_tc(const float* __restrict__ A, const float* __restrict__ B,
             const float* __restrict__ bias, float* __restrict__ Cm,
             int M, int N, int K) {
    extern __shared__ __align__(16) __nv_bfloat16 smem[];

    const int tid  = threadIdx.x;
    const int lane = tid & 31;
    const int warp = tid >> 5;
    const int wm   = warp >> 2;        // 0..1  -> rows wm*64
    const int wn   = warp & 3;         // 0..3  -> cols wn*32
    const int bx   = blockIdx.x;       // N tile
    const int by   = blockIdx.y;       // M tile

    // global load mapping: 32 rows/pass x 8 k-segments of 4 floats
    const int grow = tid >> 3;         // 0..31
    const int gseg = tid & 7;          // 0..7  (k offset = gseg*4)
    const int ssub = gseg >> 2;        // which k16 sub-tile
    const int skk  = (gseg & 3) << 2;  // k offset within sub-tile

    const float* Abase = A + (size_t)(by * 128 + grow) * K + gseg * 4;
    const float* Bbase = B + (size_t)(bx * 128 + grow) * K + gseg * 4;

    float4 pa[4], pb[4];

    // accumulators: [m-tile 0..3][n-tile 0..3][4 regs]
    float acc[4][4][4];
    #pragma unroll
    for (int i = 0; i < 4; i++)
        #pragma unroll
        for (int j = 0; j < 4; j++)
            #pragma unroll
            for (int r = 0; r < 4; r++) acc[i][j][r] = 0.0f;

    const int nIter = K >> 5;   // k-steps of 32

    // ---- global -> regs ----
    auto loadG = [&](int k0) {
        #pragma unroll
        for (int p = 0; p < 4; p++) {
            pa[p] = *(const float4*)(Abase + (size_t)(p * 32) * K + k0);
            pb[p] = *(const float4*)(Bbase + (size_t)(p * 32) * K + k0);
        }
    };

    // ---- regs -> smem (split into hi/lo bf16) ----
    auto storeS = [&](int buf) {
        __nv_bfloat16* AH = smem + buf * STAGESZ;
        __nv_bfloat16* AL = AH + ARRSZ;
        __nv_bfloat16* BH = AH + 2 * ARRSZ;
        __nv_bfloat16* BL = AH + 3 * ARRSZ;
        #pragma unroll
        for (int p = 0; p < 4; p++) {
            int r = grow + p * 32;
            int off = ssub * SUBSZ + r * GSTRIDE + skk;
            union { __nv_bfloat16 h[4]; uint2 u; } th, tl;
            const float* va = (const float*)&pa[p];
            #pragma unroll
            for (int e = 0; e < 4; e++) {
                float v = va[e];
                __nv_bfloat16 h = __float2bfloat16_rn(v);
                th.h[e] = h;
                tl.h[e] = __float2bfloat16_rn(v - __bfloat162float(h));
            }
            *(uint2*)(AH + off) = th.u;
            *(uint2*)(AL + off) = tl.u;
            const float* vb = (const float*)&pb[p];
            #pragma unroll
            for (int e = 0; e < 4; e++) {
                float v = vb[e];
                __nv_bfloat16 h = __float2bfloat16_rn(v);
                th.h[e] = h;
                tl.h[e] = __float2bfloat16_rn(v - __bfloat162float(h));
            }
            *(uint2*)(BH + off) = th.u;
            *(uint2*)(BL + off) = tl.u;
        }
    };

    // ---- compute one k32 stage ----
    auto compute = [&](int buf) {
        const __nv_bfloat16* AH = smem + buf * STAGESZ;
        const __nv_bfloat16* AL = AH + ARRSZ;
        const __nv_bfloat16* BH = AH + 2 * ARRSZ;
        const __nv_bfloat16* BL = AH + 3 * ARRSZ;
        const int lr  = lane & 15;         // ldmatrix row within tile
        const int lc  = (lane >> 4) * 8;   // ldmatrix k-half offset
        #pragma unroll
        for (int sub = 0; sub < 2; sub++) {
            uint32_t ah[4][4], al[4][4], bh[2][4], bl[2][4];
            #pragma unroll
            for (int mt = 0; mt < 4; mt++) {
                int off = sub * SUBSZ + (wm * 64 + mt * 16 + lr) * GSTRIDE + lc;
                ldsm4(ah[mt], AH + off);
                ldsm4(al[mt], AL + off);
            }
            #pragma unroll
            for (int bt = 0; bt < 2; bt++) {
                int off = sub * SUBSZ + (wn * 32 + bt * 16 + lr) * GSTRIDE + lc;
                ldsm4(bh[bt], BH + off);
                ldsm4(bl[bt], BL + off);
            }
            #pragma unroll
            for (int mt = 0; mt < 4; mt++) {
                #pragma unroll
                for (int bt = 0; bt < 2; bt++) {
                    // even n-tile (rows 0-7 of the pair): regs 0,2
                    mma_bf16(acc[mt][2 * bt],     ah[mt], bh[bt][0], bh[bt][2]);
                    mma_bf16(acc[mt][2 * bt],     ah[mt], bl[bt][0], bl[bt][2]);
                    mma_bf16(acc[mt][2 * bt],     al[mt], bh[bt][0], bh[bt][2]);
                    // odd n-tile (rows 8-15): regs 1,3
                    mma_bf16(acc[mt][2 * bt + 1], ah[mt], bh[bt][1], bh[bt][3]);
                    mma_bf16(acc[mt][2 * bt + 1], ah[mt], bl[bt][1], bl[bt][3]);
                    mma_bf16(acc[mt][2 * bt + 1], al[mt], bh[bt][1], bh[bt][3]);
                }
            }
        }
    };

    // ---- pipeline ----
    loadG(0);
    storeS(0);
    __syncthreads();
    for (int it = 0; it < nIter; it++) {
        int buf = it & 1;
        if (it + 1 < nIter) loadG((it + 1) << 5);
        compute(buf);
        __syncthreads();
        if (it + 1 < nIter) {
            storeS(buf ^ 1);
            __syncthreads();
        }
    }

    // ---- epilogue ----
    const int g   = lane >> 2;     // row group 0..7
    const int tig = lane & 3;      // col pair  0..3
    #pragma unroll
    for (int mt = 0; mt < 4; mt++) {
        int row = by * 128 + wm * 64 + mt * 16 + g;
        #pragma unroll
        for (int nt = 0; nt < 4; nt++) {
            int col = bx * 128 + wn * 32 + nt * 8 + 2 * tig;
            float b0 = bias[col], b1 = bias[col + 1];
            float2 v0 = { acc[mt][nt][0] + b0, acc[mt][nt][1] + b1 };
            float2 v1 = { acc[mt][nt][2] + b0, acc[mt][nt][3] + b1 };
            *(float2*)(Cm + (size_t)row * N + col)       = v0;
            *(float2*)(Cm + (size_t)(row + 8) * N + col) = v1;
        }
    }
}

// ---------------------------------------------------------------------------
// RoPE, in-place on q and k slices of g_qkv.
// ---------------------------------------------------------------------------
__global__ void rope_kernel(float* __restrict__ qkv,
                            const float* __restrict__ cosp,
                            const float* __restrict__ sinp) {
    int idx = blockIdx.x * blockDim.x + threadIdx.x;
    const int total = TT * NH * 2 * 16;
    if (idx >= total) return;
    int d = idx & 15;
    int m = (idx >> 4) & 1;
    int h = (idx >> 5) & 31;
    int t = idx >> 10;
    float* p = qkv + (size_t)t * QKVN + h * 384 + m * 128;
    float x1 = p[d];
    float x2 = p[d + 16];
    float c1 = cosp[t * NEr + d];
    float s1 = sinp[t * NEr + d];
    float c2 = cosp[t * NEr + d + 16];
    float s2 = sinp[t * NEr + d + 16];
    p[d]      = x1 * c1 - x2 * s1;
    p[d + 16] = x2 * c2 + x1 * s2;
}

// ---------------------------------------------------------------------------
// Causal flash attention, fp32 SIMT (unchanged from R0; next-round target).
// ---------------------------------------------------------------------------
#define QT_STRIDE 68
#define VS_STRIDE 132
#define ATTN_SMEM_FLOATS (2 * 128 * QT_STRIDE + 64 * QT_STRIDE)
#define ATTN_SMEM_BYTES  (ATTN_SMEM_FLOATS * 4)

__global__ __launch_bounds__(256)
void attn_kernel(const float* __restrict__ qkv, float* __restrict__ y) {
    const int q0 = blockIdx.x * 64;
    const int h  = blockIdx.y;

    extern __shared__ float sm[];
    float* Qt = sm;                          // [128][68]  Qt[d*68 + r]
    float* Kt = sm + 128 * QT_STRIDE;        // [128][68]  / reused as Vs[64][132]
    float* Ss = sm + 2 * 128 * QT_STRIDE;    // [64][68]

    const int tid = threadIdx.x;
    const int tx  = tid & 15;
    const int ty  = tid >> 4;
    const float scale = 0.08838834764831845f;   // 1/sqrt(128)

    for (int i = tid; i < 64 * 32; i += 256) {
        int r  = i >> 5;
        int d4 = (i & 31) << 2;
        float4 v = *(const float4*)(qkv + (size_t)(q0 + r) * QKVN + h * 384 + d4);
        Qt[(d4 + 0) * QT_STRIDE + r] = v.x * scale;
        Qt[(d4 + 1) * QT_STRIDE + r] = v.y * scale;
        Qt[(d4 + 2) * QT_STRIDE + r] = v.z * scale;
        Qt[(d4 + 3) * QT_STRIDE + r] = v.w * scale;
    }

    float m_[4], l_[4], o_[4][8];
    #pragma unroll
    for (int i = 0; i < 4; i++) {
        m_[i] = -1e30f;
        l_[i] = 0.0f;
        #pragma unroll
        for (int j = 0; j < 8; j++) o_[i][j] = 0.0f;
    }

    for (int k0 = 0; k0 <= q0; k0 += 64) {
        __syncthreads();

        for (int i = tid; i < 64 * 32; i += 256) {
            int r  = i >> 5;
            int d4 = (i & 31) << 2;
            float4 v = *(const float4*)(qkv + (size_t)(k0 + r) * QKVN + h * 384 + 128 + d4);
            Kt[(d4 + 0) * QT_STRIDE + r] = v.x;
            Kt[(d4 + 1) * QT_STRIDE + r] = v.y;
            Kt[(d4 + 2) * QT_STRIDE + r] = v.z;
            Kt[(d4 + 3) * QT_STRIDE + r] = v.w;
        }
        __syncthreads();

        float acc[4][4];
        #pragma unroll
        for (int i = 0; i < 4; i++)
            #pragma unroll
            for (int j = 0; j < 4; j++) acc[i][j] = 0.0f;

        #pragma unroll 4
        for (int d = 0; d < 128; d++) {
            float4 a4 = *(const float4*)(Qt + d * QT_STRIDE + (ty << 2));
            float4 b4 = *(const float4*)(Kt + d * QT_STRIDE + (tx << 2));
            float a[4] = {a4.x, a4.y, a4.z, a4.w};
            float b[4] = {b4.x, b4.y, b4.z, b4.w};
            #pragma unroll
            for (int i = 0; i < 4; i++)
                #pragma unroll
                for (int j = 0; j < 4; j++)
                    acc[i][j] += a[i] * b[j];
        }

        if (k0 == q0) {
            #pragma unroll
            for (int i = 0; i < 4; i++)
                #pragma unroll
                for (int j = 0; j < 4; j++)
                    if ((tx << 2) + j > (ty << 2) + i) acc[i][j] = -1e30f;
        }

        #pragma unroll
        for (int i = 0; i < 4; i++) {
            float mx = fmaxf(fmaxf(acc[i][0], acc[i][1]), fmaxf(acc[i][2], acc[i][3]));
            #pragma unroll
            for (int ofs = 8; ofs >= 1; ofs >>= 1)
                mx = fmaxf(mx, __shfl_xor_sync(0xffffffffu, mx, ofs));
            float mn = fmaxf(m_[i], mx);
            float al = __expf(m_[i] - mn);
            float sum = 0.0f;
            #pragma unroll
            for (int j = 0; j < 4; j++) {
                float p = __expf(acc[i][j] - mn);
                acc[i][j] = p;
                sum += p;
            }
            #pragma unroll
            for (int ofs = 8; ofs >= 1; ofs >>= 1)
                sum += __shfl_xor_sync(0xffffffffu, sum, ofs);
            l_[i] = l_[i] * al + sum;
            m_[i] = mn;
            #pragma unroll
            for (int j = 0; j < 8; j++) o_[i][j] *= al;
            #pragma unroll
            for (int j = 0; j < 4; j++)
                Ss[((ty << 2) + i) * QT_STRIDE + (tx << 2) + j] = acc[i][j];
        }
        __syncthreads();

        float* Vs = Kt;
        for (int i = tid; i < 64 * 32; i += 256) {
            int r  = i >> 5;
            int d4 = (i & 31) << 2;
            *(float4*)(Vs + r * VS_STRIDE + d4) =
                *(const float4*)(qkv + (size_t)(k0 + r) * QKVN + h * 384 + 256 + d4);
        }
        __syncthreads();

        for (int kk = 0; kk < 64; kk += 4) {
            float pr[4][4];
            #pragma unroll
            for (int i = 0; i < 4; i++)
                *(float4*)&pr[i][0] =
                    *(const float4*)&Ss[((ty << 2) + i) * QT_STRIDE + kk];
            #pragma unroll
            for (int c = 0; c < 4; c++) {
                float4 v0 = *(const float4*)(Vs + (kk + c) * VS_STRIDE + (tx << 3));
                float4 v1 = *(const float4*)(Vs + (kk + c) * VS_STRIDE + (tx << 3) + 4);
                #pragma unroll
                for (int i = 0; i < 4; i++) {
                    float p = pr[i][c];
                    o_[i][0] += p * v0.x;  o_[i][1] += p * v0.y;
                    o_[i][2] += p * v0.z;  o_[i][3] += p * v0.w;
                    o_[i][4] += p * v1.x;  o_[i][5] += p * v1.y;
                    o_[i][6] += p * v1.z;  o_[i][7] += p * v1.w;
                }
            }
        }
    }

    #pragma unroll
    for (int i = 0; i < 4; i++) {
        float inv = 1.0f / l_[i];
        int r = q0 + (ty << 2) + i;
        float4 w0, w1;
        w0.x = o_[i][0] * inv;  w0.y = o_[i][1] * inv;
        w0.z = o_[i][2] * inv;  w0.w = o_[i][3] * inv;
        w1.x = o_[i][4] * inv;  w1.y = o_[i][5] * inv;
        w1.z = o_[i][6] * inv;  w1.w = o_[i][7] * inv;
        *(float4*)(y + (size_t)r * CC + h * HS + (tx << 3))     = w0;
        *(float4*)(y + (size_t)r * CC + h * HS + (tx << 3) + 4) = w1;
    }
}

// ---------------------------------------------------------------------------
// Launch
// ---------------------------------------------------------------------------
extern "C" void kernel_launch(void* const* d_in, const int* in_sizes, int n_in,
                              void* d_out, int out_size) {
    const float* x      = (const float*)d_in[0];
    const float* cosp   = (const float*)d_in[1];
    const float* sinp   = (const float*)d_in[2];
    const float* W_attn = (const float*)d_in[3];
    const float* b_attn = (const float*)d_in[4];
    const float* W_proj = (const float*)d_in[5];
    const float* b_proj = (const float*)d_in[6];
    float* out = (float*)d_out;

    float *qkv_p, *y_p;
    cudaGetSymbolAddress((void**)&qkv_p, g_qkv);
    cudaGetSymbolAddress((void**)&y_p, g_y);

    cudaFuncSetAttribute(gemm_tc,
                         cudaFuncAttributeMaxDynamicSharedMemorySize,
                         GEMM_SMEM_BYTES);
    cudaFuncSetAttribute(attn_kernel,
                         cudaFuncAttributeMaxDynamicSharedMemorySize,
                         ATTN_SMEM_BYTES);

    // 1) QKV = x @ W_attn^T + b_attn        [2048, 12288]
    gemm_tc<<<dim3(QKVN / 128, TT / 128), 256, GEMM_SMEM_BYTES>>>(
        x, W_attn, b_attn, qkv_p, TT, QKVN, CC);

    // 2) RoPE in-place on q, k
    rope_kernel<<<(TT * NH * 2 * 16) / 256, 256>>>(qkv_p, cosp, sinp);

    // 3) Causal attention -> y              [2048, 4096]
    attn_kernel<<<dim3(TT / 64, NH), 256, ATTN_SMEM_BYTES>>>(qkv_p, y_p);

    // 4) out = y @ W_proj^T + b_proj        [2048, 4096]
    gemm_tc<<<dim3(CC / 128, TT / 128), 256, GEMM_SMEM_BYTES>>>(
        y_p, W_proj, b_proj, out, TT, CC, CC);
}